// round 16
// baseline (speedup 1.0000x reference)
#include <cuda_runtime.h>
#include <cuda_fp16.h>
#include <stdint.h>

#define NMAX 700000
#define EMAX 4000000
#define SLOT 32   // max in-degree slots per node (Poisson(5.7): P(exceed) ~ 1e-8)

// Scratch (__device__ globals; allocation-free rule)
__device__ int     g_len[NMAX];               // in-degree; doubles as fill cursor
__device__ int     g_srcs[(size_t)NMAX * SLOT];  // slot-CSR: srcs of node d at d*SLOT
__device__ float   g_dinv[NMAX];
__device__ __half2 g_h[(size_t)NMAX * 32];    // h1 (UNscaled) then hs2 (scaled), in place
__device__ __half2 g_agg[(size_t)NMAX * 32];  // layer-1 aggregate, half2

// ---------------------------------------------------------------------------
// MMA helpers
__device__ __forceinline__ uint32_t smem_u32(const void* p) {
    return (uint32_t)__cvta_generic_to_shared(p);
}
__device__ __forceinline__ void ldsm_x4(uint32_t& a0, uint32_t& a1, uint32_t& a2,
                                        uint32_t& a3, uint32_t addr) {
    asm volatile("ldmatrix.sync.aligned.m8n8.x4.shared.b16 {%0,%1,%2,%3}, [%4];"
                 : "=r"(a0), "=r"(a1), "=r"(a2), "=r"(a3) : "r"(addr));
}
__device__ __forceinline__ void ldsm_x2t(uint32_t& b0, uint32_t& b1, uint32_t addr) {
    asm volatile("ldmatrix.sync.aligned.m8n8.x2.trans.shared.b16 {%0,%1}, [%2];"
                 : "=r"(b0), "=r"(b1) : "r"(addr));
}
__device__ __forceinline__ void mma16816(float* d, uint32_t a0, uint32_t a1, uint32_t a2,
                                         uint32_t a3, uint32_t b0, uint32_t b1) {
    asm volatile(
        "mma.sync.aligned.m16n8k16.row.col.f32.f16.f16.f32 "
        "{%0,%1,%2,%3}, {%4,%5,%6,%7}, {%8,%9}, {%0,%1,%2,%3};"
        : "+f"(d[0]), "+f"(d[1]), "+f"(d[2]), "+f"(d[3])
        : "r"(a0), "r"(a1), "r"(a2), "r"(a3), "r"(b0), "r"(b1));
}

// ---------------------------------------------------------------------------
__global__ void k_zero_len(int n) {
    int i = blockIdx.x * blockDim.x + threadIdx.x;
    if (i < n) g_len[i] = 0;
}

// Single-pass slot-CSR build: count + place in one atomic.
__global__ void k_fill_direct4(const int4* __restrict__ src4,
                               const int4* __restrict__ dst4, int E4) {
    int i = blockIdx.x * blockDim.x + threadIdx.x;
    if (i < E4) {
        int4 s = __ldg(&src4[i]);
        int4 d = __ldg(&dst4[i]);
        int p;
        p = atomicAdd(&g_len[d.x], 1); if (p < SLOT) g_srcs[(size_t)d.x * SLOT + p] = s.x;
        p = atomicAdd(&g_len[d.y], 1); if (p < SLOT) g_srcs[(size_t)d.y * SLOT + p] = s.y;
        p = atomicAdd(&g_len[d.z], 1); if (p < SLOT) g_srcs[(size_t)d.z * SLOT + p] = s.z;
        p = atomicAdd(&g_len[d.w], 1); if (p < SLOT) g_srcs[(size_t)d.w * SLOT + p] = s.w;
    }
}

__global__ void k_fill_tail(const int* __restrict__ src, const int* __restrict__ dst,
                            int off, int E) {
    int e = off + blockIdx.x * blockDim.x + threadIdx.x;
    if (e < E) {
        int d = dst[e];
        int p = atomicAdd(&g_len[d], 1);
        if (p < SLOT) g_srcs[(size_t)d * SLOT + p] = src[e];
    }
}

__global__ void k_dinv(int n) {
    int i = blockIdx.x * blockDim.x + threadIdx.x;
    if (i < n) g_dinv[i] = rsqrtf((float)(g_len[i] + 1));
}

// ---------------------------------------------------------------------------
// Tensor-core gemm1: h1 = x @ W1 (UNSCALED), half2 out. Overlaps CSR build on s2.
__global__ __launch_bounds__(256) void k_gemm1_mma(const float* __restrict__ x,
                                                   const float* __restrict__ W1, int n) {
    __shared__ __half Xs[128 * 40];   // row stride 40 halves (pad)
    __shared__ __half Ws[32 * 72];    // W1[k][c], stride 72
    int tid = threadIdx.x;
    for (int i = tid; i < 32 * 64; i += 256) {
        int k = i >> 6, c = i & 63;
        Ws[k * 72 + c] = __float2half(W1[i]);
    }
    int r0blk = blockIdx.x * 128;
    int p = tid & 15, rowsub = tid >> 4;
#pragma unroll
    for (int it = 0; it < 8; it++) {
        int r = rowsub + it * 16;
        int gr = r0blk + r;
        float2 v = (gr < n) ? *(const float2*)(x + (size_t)gr * 32 + p * 2)
                            : make_float2(0.f, 0.f);
        *(__half2*)&Xs[r * 40 + p * 2] = __floats2half2_rn(v.x, v.y);
    }
    __syncthreads();
    int warp = tid >> 5, lane = tid & 31;
    int rw = warp * 16;
    float acc[8][4];
#pragma unroll
    for (int nn = 0; nn < 8; nn++)
        acc[nn][0] = acc[nn][1] = acc[nn][2] = acc[nn][3] = 0.f;
#pragma unroll
    for (int kk = 0; kk < 2; kk++) {
        uint32_t a0, a1, a2, a3;
        uint32_t aaddr = smem_u32(&Xs[(rw + (lane & 15)) * 40 + kk * 16 + (lane >> 4) * 8]);
        ldsm_x4(a0, a1, a2, a3, aaddr);
#pragma unroll
        for (int nn = 0; nn < 8; nn++) {
            uint32_t b0, b1;
            uint32_t baddr = smem_u32(&Ws[(kk * 16 + (lane & 15)) * 72 + nn * 8]);
            ldsm_x2t(b0, b1, baddr);
            mma16816(acc[nn], a0, a1, a2, a3, b0, b1);
        }
    }
    int g = lane >> 2, t4 = lane & 3;
    int r1 = r0blk + rw + g, r2 = r1 + 8;
    bool v1 = r1 < n, v2 = r2 < n;
#pragma unroll
    for (int nn = 0; nn < 8; nn++) {
        if (v1) g_h[(size_t)r1 * 32 + nn * 4 + t4] =
            __floats2half2_rn(acc[nn][0], acc[nn][1]);
        if (v2) g_h[(size_t)r2 * 32 + nn * 4 + t4] =
            __floats2half2_rn(acc[nn][2], acc[nn][3]);
    }
}

// Tensor-core gemm2: hs2 = (relu(agg + b1) @ W2) * dinv, in-place over g_h.
__global__ __launch_bounds__(256) void k_gemm2_mma(const float* __restrict__ W2,
                                                   const float* __restrict__ b1, int n) {
    __shared__ __half Xs[128 * 72];
    __shared__ __half Ws[64 * 72];
    int tid = threadIdx.x;
    for (int i = tid; i < 64 * 64; i += 256) {
        int k = i >> 6, c = i & 63;
        Ws[k * 72 + c] = __float2half(W2[i]);
    }
    int r0blk = blockIdx.x * 128;
#pragma unroll
    for (int it = 0; it < 16; it++) {
        int i = tid + it * 256;
        int r = i >> 5, c = i & 31;
        int gr = r0blk + r;
        float2 v;
        if (gr < n) {
            __half2 h = __ldcs(&g_agg[(size_t)gr * 32 + c]);  // evict-first
            float2 f = __half22float2(h);
            v.x = fmaxf(f.x + __ldg(&b1[c * 2]), 0.f);
            v.y = fmaxf(f.y + __ldg(&b1[c * 2 + 1]), 0.f);
        } else {
            v.x = 0.f; v.y = 0.f;
        }
        *(__half2*)&Xs[r * 72 + c * 2] = __floats2half2_rn(v.x, v.y);
    }
    __syncthreads();
    int warp = tid >> 5, lane = tid & 31;
    int rw = warp * 16;
    float acc[8][4];
#pragma unroll
    for (int nn = 0; nn < 8; nn++)
        acc[nn][0] = acc[nn][1] = acc[nn][2] = acc[nn][3] = 0.f;
#pragma unroll
    for (int kk = 0; kk < 4; kk++) {
        uint32_t a0, a1, a2, a3;
        uint32_t aaddr = smem_u32(&Xs[(rw + (lane & 15)) * 72 + kk * 16 + (lane >> 4) * 8]);
        ldsm_x4(a0, a1, a2, a3, aaddr);
#pragma unroll
        for (int nn = 0; nn < 8; nn++) {
            uint32_t b0, b1;
            uint32_t baddr = smem_u32(&Ws[(kk * 16 + (lane & 15)) * 72 + nn * 8]);
            ldsm_x2t(b0, b1, baddr);
            mma16816(acc[nn], a0, a1, a2, a3, b0, b1);
        }
    }
    int g = lane >> 2, t4 = lane & 3;
    int r1 = r0blk + rw + g, r2 = r1 + 8;
    bool v1 = r1 < n, v2 = r2 < n;
    float di1 = v1 ? g_dinv[r1] : 0.f;
    float di2 = v2 ? g_dinv[r2] : 0.f;
#pragma unroll
    for (int nn = 0; nn < 8; nn++) {
        if (v1) g_h[(size_t)r1 * 32 + nn * 4 + t4] =
            __floats2half2_rn(acc[nn][0] * di1, acc[nn][1] * di1);
        if (v2) g_h[(size_t)r2 * 32 + nn * 4 + t4] =
            __floats2half2_rn(acc[nn][2] * di2, acc[nn][3] * di2);
    }
}

// ---------------------------------------------------------------------------
__device__ __forceinline__ void acc_fma(float* acc, uint4 v, float di) {
    float2 f0 = __half22float2(*reinterpret_cast<__half2*>(&v.x));
    float2 f1 = __half22float2(*reinterpret_cast<__half2*>(&v.y));
    float2 f2 = __half22float2(*reinterpret_cast<__half2*>(&v.z));
    float2 f3 = __half22float2(*reinterpret_cast<__half2*>(&v.w));
    acc[0] = fmaf(di, f0.x, acc[0]); acc[1] = fmaf(di, f0.y, acc[1]);
    acc[2] = fmaf(di, f1.x, acc[2]); acc[3] = fmaf(di, f1.y, acc[3]);
    acc[4] = fmaf(di, f2.x, acc[4]); acc[5] = fmaf(di, f2.y, acc[5]);
    acc[6] = fmaf(di, f3.x, acc[6]); acc[7] = fmaf(di, f3.y, acc[7]);
}

__device__ __forceinline__ void acc_add(float* acc, uint4 v) {
    float2 f0 = __half22float2(*reinterpret_cast<__half2*>(&v.x));
    float2 f1 = __half22float2(*reinterpret_cast<__half2*>(&v.y));
    float2 f2 = __half22float2(*reinterpret_cast<__half2*>(&v.z));
    float2 f3 = __half22float2(*reinterpret_cast<__half2*>(&v.w));
    acc[0] += f0.x; acc[1] += f0.y;
    acc[2] += f1.x; acc[3] += f1.y;
    acc[4] += f2.x; acc[5] += f2.y;
    acc[6] += f3.x; acc[7] += f3.y;
}

// gather layer 1 over UNscaled h1:
// agg[d] = dinv[d]*(dinv[d]*h1[d] + sum dinv[s]*h1[s]) -> g_agg (half2, streaming).
// 4 nodes per warp, 8 lanes (16B each) per node.
__global__ void k_gather1(int n) {
    int warp = threadIdx.x >> 5, lane = threadIdx.x & 31;
    int grp = lane >> 3, sub = lane & 7;
    int d = (blockIdx.x * 8 + warp) * 4 + grp;
    bool active = d < n;
    int len = 0;
    float di_d = 0.f;
    if (active) { len = min(g_len[d], SLOT); di_d = g_dinv[d]; }
    const int* srow = g_srcs + (size_t)d * SLOT;
    float acc[8] = {0, 0, 0, 0, 0, 0, 0, 0};
    if (active) acc_fma(acc, __ldg((const uint4*)g_h + (size_t)d * 8 + sub), di_d);  // self
    int maxlen = len;
    maxlen = max(maxlen, __shfl_xor_sync(0xffffffffu, maxlen, 8));
    maxlen = max(maxlen, __shfl_xor_sync(0xffffffffu, maxlen, 16));
    for (int j0 = 0; j0 < maxlen; j0 += 8) {
        int rem = len - j0;
        int sidx = (sub < rem) ? __ldcs(&srow[j0 + sub]) : -1;
#pragma unroll
        for (int j = 0; j < 8; j++) {
            int s = __shfl_sync(0xffffffffu, sidx, grp * 8 + j);
            if (s >= 0) {
                float di = __ldg(&g_dinv[s]);
                acc_fma(acc, __ldg((const uint4*)g_h + (size_t)s * 8 + sub), di);
            }
        }
    }
    if (active) {
        __half2 p0 = __floats2half2_rn(acc[0] * di_d, acc[1] * di_d);
        __half2 p1 = __floats2half2_rn(acc[2] * di_d, acc[3] * di_d);
        __half2 p2 = __floats2half2_rn(acc[4] * di_d, acc[5] * di_d);
        __half2 p3 = __floats2half2_rn(acc[6] * di_d, acc[7] * di_d);
        uint4 o;
        o.x = *reinterpret_cast<uint32_t*>(&p0);
        o.y = *reinterpret_cast<uint32_t*>(&p1);
        o.z = *reinterpret_cast<uint32_t*>(&p2);
        o.w = *reinterpret_cast<uint32_t*>(&p3);
        __stwt((uint4*)g_agg + (size_t)d * 8 + sub, o);  // bypass L2 (protect g_h)
    }
}

__global__ void k_out_init(const float* __restrict__ bfc, float* __restrict__ out, int B) {
    int g = blockIdx.x * blockDim.x + threadIdx.x;
    if (g < B) out[g] = bfc[0];
}

// gather layer 2 (hs2 pre-scaled) + relu+b2 + FC head.
__global__ void k_gather2_fc(const float* __restrict__ b2, const float* __restrict__ Wfc,
                             float* __restrict__ out, int n) {
    int warp = threadIdx.x >> 5, lane = threadIdx.x & 31;
    int grp = lane >> 3, sub = lane & 7;
    int d = (blockIdx.x * 8 + warp) * 4 + grp;
    bool active = d < n;
    int len = 0;
    if (active) len = min(g_len[d], SLOT);
    const int* srow = g_srcs + (size_t)d * SLOT;
    float acc[8] = {0, 0, 0, 0, 0, 0, 0, 0};
    if (active) acc_add(acc, __ldg((const uint4*)g_h + (size_t)d * 8 + sub));  // self
    int maxlen = len;
    maxlen = max(maxlen, __shfl_xor_sync(0xffffffffu, maxlen, 8));
    maxlen = max(maxlen, __shfl_xor_sync(0xffffffffu, maxlen, 16));
    for (int j0 = 0; j0 < maxlen; j0 += 8) {
        int rem = len - j0;
        int sidx = (sub < rem) ? __ldcs(&srow[j0 + sub]) : -1;
#pragma unroll
        for (int j = 0; j < 8; j++) {
            int s = __shfl_sync(0xffffffffu, sidx, grp * 8 + j);
            if (s >= 0)
                acc_add(acc, __ldg((const uint4*)g_h + (size_t)s * 8 + sub));
        }
    }
    float p = 0.f;
    if (active) {
        float di = g_dinv[d];
        int pos = d % 14;
        const float* wrow = Wfc + pos * 64 + sub * 8;
        const float* brow = b2 + sub * 8;
#pragma unroll
        for (int i = 0; i < 8; i++) {
            float t = fmaxf(fmaf(acc[i], di, __ldg(brow + i)), 0.f);
            p = fmaf(t, __ldg(wrow + i), p);
        }
    }
    p += __shfl_down_sync(0xffffffffu, p, 4, 8);
    p += __shfl_down_sync(0xffffffffu, p, 2, 8);
    p += __shfl_down_sync(0xffffffffu, p, 1, 8);
    if (active && sub == 0) atomicAdd(&out[d / 14], p);
}

// ---------------------------------------------------------------------------
extern "C" void kernel_launch(void* const* d_in, const int* in_sizes, int n_in,
                              void* d_out, int out_size) {
    const float* x     = (const float*)d_in[0];
    const int*   edges = (const int*)d_in[1];   // int32 (JAX x64 disabled)
    const float* W1    = (const float*)d_in[2];
    const float* b1    = (const float*)d_in[3];
    const float* W2    = (const float*)d_in[4];
    const float* b2    = (const float*)d_in[5];
    const float* Wfc   = (const float*)d_in[6];
    const float* bfc   = (const float*)d_in[7];
    float* out = (float*)d_out;

    int n = in_sizes[0] / 32;   // 700000
    int E = in_sizes[1] / 2;    // 4000000
    int B = n / 14;             // 50000
    const int* src = edges;
    const int* dst = edges + E;
    int E4 = E / 4, Etail = E - E4 * 4;

    // One-time host-side setup (first call = correctness run, outside capture).
    static cudaStream_t s2 = nullptr;
    static cudaEvent_t e0 = nullptr, e2 = nullptr;
    if (!s2) {
        cudaStreamCreateWithFlags(&s2, cudaStreamNonBlocking);
        cudaEventCreateWithFlags(&e0, cudaEventDisableTiming);
        cudaEventCreateWithFlags(&e2, cudaEventDisableTiming);
    }

    // Fork FIRST (capture-legal): s2 must join the capture via an event
    // recorded on the capturing stream before any s2 launch.
    cudaEventRecord(e0, 0);
    cudaStreamWaitEvent(s2, e0, 0);
    k_gemm1_mma<<<(n + 127) / 128, 256, 0, s2>>>(x, W1, n);
    k_out_init<<<(B + 255) / 256, 256, 0, s2>>>(bfc, out, B);
    cudaEventRecord(e2, s2);

    // Launch stream: single-pass slot-CSR build + dinv (overlaps gemm1)
    k_zero_len<<<(n + 255) / 256, 256>>>(n);
    k_fill_direct4<<<(E4 + 255) / 256, 256>>>((const int4*)src, (const int4*)dst, E4);
    if (Etail) k_fill_tail<<<1, 256>>>(src, dst, E4 * 4, E);
    k_dinv<<<(n + 255) / 256, 256>>>(n);

    // Join gemm1
    cudaStreamWaitEvent(0, e2, 0);

    // Layer 1 gather (applies dinv[s] per neighbor)
    k_gather1<<<(n + 31) / 32, 256>>>(n);

    // Layer 2 (tensor core)
    k_gemm2_mma<<<(n + 127) / 128, 256>>>(W2, b1, n);

    // FC head fused into layer-2 gather
    k_gather2_fc<<<(n + 31) / 32, 256>>>(b2, Wfc, out, n);
}

// round 17
// speedup vs baseline: 1.1358x; 1.1358x over previous
#include <cuda_runtime.h>
#include <cuda_fp16.h>
#include <stdint.h>

#define NMAX 700000
#define EMAX 4000000
#define SCAN_B 1024

// Scratch (__device__ globals; allocation-free rule)
__device__ int     g_cnt[NMAX];
__device__ int     g_rowptr[NMAX];
__device__ int     g_cursor[NMAX];     // preloaded with rowptr; fill bumps it
__device__ int     g_srcs[EMAX];
__device__ int     g_bsum[SCAN_B];
__device__ float   g_dinv[NMAX];
__device__ __half2 g_h[(size_t)NMAX * 32];    // hs1 then hs2 (overwritten in place)
__device__ __half2 g_agg[(size_t)NMAX * 32];  // layer-1 aggregate, half2

// ---------------------------------------------------------------------------
// MMA helpers
__device__ __forceinline__ uint32_t smem_u32(const void* p) {
    return (uint32_t)__cvta_generic_to_shared(p);
}
__device__ __forceinline__ void ldsm_x4(uint32_t& a0, uint32_t& a1, uint32_t& a2,
                                        uint32_t& a3, uint32_t addr) {
    asm volatile("ldmatrix.sync.aligned.m8n8.x4.shared.b16 {%0,%1,%2,%3}, [%4];"
                 : "=r"(a0), "=r"(a1), "=r"(a2), "=r"(a3) : "r"(addr));
}
__device__ __forceinline__ void ldsm_x2t(uint32_t& b0, uint32_t& b1, uint32_t addr) {
    asm volatile("ldmatrix.sync.aligned.m8n8.x2.trans.shared.b16 {%0,%1}, [%2];"
                 : "=r"(b0), "=r"(b1) : "r"(addr));
}
__device__ __forceinline__ void mma16816(float* d, uint32_t a0, uint32_t a1, uint32_t a2,
                                         uint32_t a3, uint32_t b0, uint32_t b1) {
    asm volatile(
        "mma.sync.aligned.m16n8k16.row.col.f32.f16.f16.f32 "
        "{%0,%1,%2,%3}, {%4,%5,%6,%7}, {%8,%9}, {%0,%1,%2,%3};"
        : "+f"(d[0]), "+f"(d[1]), "+f"(d[2]), "+f"(d[3])
        : "r"(a0), "r"(a1), "r"(a2), "r"(a3), "r"(b0), "r"(b1));
}

// ---------------------------------------------------------------------------
__global__ void k_zero_cnt(int n) {
    int i = blockIdx.x * blockDim.x + threadIdx.x;
    if (i < n) g_cnt[i] = 0;
}

__global__ void k_cnt4(const int4* __restrict__ dst4, int E4) {
    int i = blockIdx.x * blockDim.x + threadIdx.x;
    if (i < E4) {
        int4 d = __ldg(&dst4[i]);
        atomicAdd(&g_cnt[d.x], 1);
        atomicAdd(&g_cnt[d.y], 1);
        atomicAdd(&g_cnt[d.z], 1);
        atomicAdd(&g_cnt[d.w], 1);
    }
}

__global__ void k_cnt_tail(const int* __restrict__ dst, int off, int E) {
    int e = off + blockIdx.x * blockDim.x + threadIdx.x;
    if (e < E) atomicAdd(&g_cnt[dst[e]], 1);
}

// Block-local exclusive scan of cnt -> rowptr (pre-offset), block sums -> bsum.
// FUSED: dinv = rsqrt(cnt+1).
__global__ void k_scan1(int n) {
    __shared__ int sh[SCAN_B];
    int i = blockIdx.x * SCAN_B + threadIdx.x;
    int v = (i < n) ? g_cnt[i] : 0;
    sh[threadIdx.x] = v;
    __syncthreads();
    for (int off = 1; off < SCAN_B; off <<= 1) {
        int t = (threadIdx.x >= off) ? sh[threadIdx.x - off] : 0;
        __syncthreads();
        sh[threadIdx.x] += t;
        __syncthreads();
    }
    if (i < n) {
        g_rowptr[i] = sh[threadIdx.x] - v;  // exclusive, block-local
        g_dinv[i] = rsqrtf((float)(v + 1));
    }
    if (threadIdx.x == SCAN_B - 1) g_bsum[blockIdx.x] = sh[SCAN_B - 1];
}

// Finalize rowptr with cross-block offset (merged scan2), seed cursor = rowptr.
__global__ void k_scan3(int n) {
    __shared__ int boff_sh;
    int q = (blockIdx.x * 256) / SCAN_B;   // # of preceding scan blocks
    if (threadIdx.x < 32) {
        int s = 0;
        for (int k = threadIdx.x; k < q; k += 32) s += g_bsum[k];
#pragma unroll
        for (int o = 16; o; o >>= 1) s += __shfl_down_sync(0xffffffffu, s, o);
        if (threadIdx.x == 0) boff_sh = s;
    }
    __syncthreads();
    int i = blockIdx.x * 256 + threadIdx.x;
    if (i < n) {
        int rp = g_rowptr[i] + boff_sh;
        g_rowptr[i] = rp;
        g_cursor[i] = rp;
    }
}

__global__ void k_fill4(const int4* __restrict__ src4, const int4* __restrict__ dst4, int E4) {
    int i = blockIdx.x * blockDim.x + threadIdx.x;
    if (i < E4) {
        int4 s = __ldg(&src4[i]);
        int4 d = __ldg(&dst4[i]);
        g_srcs[atomicAdd(&g_cursor[d.x], 1)] = s.x;
        g_srcs[atomicAdd(&g_cursor[d.y], 1)] = s.y;
        g_srcs[atomicAdd(&g_cursor[d.z], 1)] = s.z;
        g_srcs[atomicAdd(&g_cursor[d.w], 1)] = s.w;
    }
}

__global__ void k_fill_tail(const int* __restrict__ src, const int* __restrict__ dst,
                            int off, int E) {
    int e = off + blockIdx.x * blockDim.x + threadIdx.x;
    if (e < E) g_srcs[atomicAdd(&g_cursor[dst[e]], 1)] = src[e];
}

// ---------------------------------------------------------------------------
// Tensor-core gemm1: hs1 = (x @ W1) * dinv, half2 out. 128 rows/block, 16/warp.
__global__ __launch_bounds__(256) void k_gemm1_mma(const float* __restrict__ x,
                                                   const float* __restrict__ W1, int n) {
    __shared__ __half Xs[128 * 40];   // row stride 40 halves (pad)
    __shared__ __half Ws[32 * 72];    // W1[k][c], stride 72
    int tid = threadIdx.x;
    for (int i = tid; i < 32 * 64; i += 256) {
        int k = i >> 6, c = i & 63;
        Ws[k * 72 + c] = __float2half(W1[i]);
    }
    int r0blk = blockIdx.x * 128;
    int p = tid & 15, rowsub = tid >> 4;
#pragma unroll
    for (int it = 0; it < 8; it++) {
        int r = rowsub + it * 16;
        int gr = r0blk + r;
        float2 v = (gr < n) ? *(const float2*)(x + (size_t)gr * 32 + p * 2)
                            : make_float2(0.f, 0.f);
        *(__half2*)&Xs[r * 40 + p * 2] = __floats2half2_rn(v.x, v.y);
    }
    __syncthreads();
    int warp = tid >> 5, lane = tid & 31;
    int rw = warp * 16;
    float acc[8][4];
#pragma unroll
    for (int nn = 0; nn < 8; nn++)
        acc[nn][0] = acc[nn][1] = acc[nn][2] = acc[nn][3] = 0.f;
#pragma unroll
    for (int kk = 0; kk < 2; kk++) {
        uint32_t a0, a1, a2, a3;
        uint32_t aaddr = smem_u32(&Xs[(rw + (lane & 15)) * 40 + kk * 16 + (lane >> 4) * 8]);
        ldsm_x4(a0, a1, a2, a3, aaddr);
#pragma unroll
        for (int nn = 0; nn < 8; nn++) {
            uint32_t b0, b1;
            uint32_t baddr = smem_u32(&Ws[(kk * 16 + (lane & 15)) * 72 + nn * 8]);
            ldsm_x2t(b0, b1, baddr);
            mma16816(acc[nn], a0, a1, a2, a3, b0, b1);
        }
    }
    int g = lane >> 2, t4 = lane & 3;
    int r1 = r0blk + rw + g, r2 = r1 + 8;
    bool v1 = r1 < n, v2 = r2 < n;
    float di1 = v1 ? g_dinv[r1] : 0.f;
    float di2 = v2 ? g_dinv[r2] : 0.f;
#pragma unroll
    for (int nn = 0; nn < 8; nn++) {
        if (v1) g_h[(size_t)r1 * 32 + nn * 4 + t4] =
            __floats2half2_rn(acc[nn][0] * di1, acc[nn][1] * di1);
        if (v2) g_h[(size_t)r2 * 32 + nn * 4 + t4] =
            __floats2half2_rn(acc[nn][2] * di2, acc[nn][3] * di2);
    }
}

// Tensor-core gemm2: hs2 = (relu(agg + b1) @ W2) * dinv, in-place over g_h.
__global__ __launch_bounds__(256) void k_gemm2_mma(const float* __restrict__ W2,
                                                   const float* __restrict__ b1, int n) {
    __shared__ __half Xs[128 * 72];
    __shared__ __half Ws[64 * 72];
    int tid = threadIdx.x;
    for (int i = tid; i < 64 * 64; i += 256) {
        int k = i >> 6, c = i & 63;
        Ws[k * 72 + c] = __float2half(W2[i]);
    }
    int r0blk = blockIdx.x * 128;
#pragma unroll
    for (int it = 0; it < 16; it++) {
        int i = tid + it * 256;
        int r = i >> 5, c = i & 31;
        int gr = r0blk + r;
        float2 v;
        if (gr < n) {
            __half2 h = __ldcs(&g_agg[(size_t)gr * 32 + c]);  // evict-first
            float2 f = __half22float2(h);
            v.x = fmaxf(f.x + __ldg(&b1[c * 2]), 0.f);
            v.y = fmaxf(f.y + __ldg(&b1[c * 2 + 1]), 0.f);
        } else {
            v.x = 0.f; v.y = 0.f;
        }
        *(__half2*)&Xs[r * 72 + c * 2] = __floats2half2_rn(v.x, v.y);
    }
    __syncthreads();
    int warp = tid >> 5, lane = tid & 31;
    int rw = warp * 16;
    float acc[8][4];
#pragma unroll
    for (int nn = 0; nn < 8; nn++)
        acc[nn][0] = acc[nn][1] = acc[nn][2] = acc[nn][3] = 0.f;
#pragma unroll
    for (int kk = 0; kk < 4; kk++) {
        uint32_t a0, a1, a2, a3;
        uint32_t aaddr = smem_u32(&Xs[(rw + (lane & 15)) * 72 + kk * 16 + (lane >> 4) * 8]);
        ldsm_x4(a0, a1, a2, a3, aaddr);
#pragma unroll
        for (int nn = 0; nn < 8; nn++) {
            uint32_t b0, b1;
            uint32_t baddr = smem_u32(&Ws[(kk * 16 + (lane & 15)) * 72 + nn * 8]);
            ldsm_x2t(b0, b1, baddr);
            mma16816(acc[nn], a0, a1, a2, a3, b0, b1);
        }
    }
    int g = lane >> 2, t4 = lane & 3;
    int r1 = r0blk + rw + g, r2 = r1 + 8;
    bool v1 = r1 < n, v2 = r2 < n;
    float di1 = v1 ? g_dinv[r1] : 0.f;
    float di2 = v2 ? g_dinv[r2] : 0.f;
#pragma unroll
    for (int nn = 0; nn < 8; nn++) {
        if (v1) g_h[(size_t)r1 * 32 + nn * 4 + t4] =
            __floats2half2_rn(acc[nn][0] * di1, acc[nn][1] * di1);
        if (v2) g_h[(size_t)r2 * 32 + nn * 4 + t4] =
            __floats2half2_rn(acc[nn][2] * di2, acc[nn][3] * di2);
    }
}

// ---------------------------------------------------------------------------
__device__ __forceinline__ void acc_add(float* acc, uint4 v) {
    float2 f0 = __half22float2(*reinterpret_cast<__half2*>(&v.x));
    float2 f1 = __half22float2(*reinterpret_cast<__half2*>(&v.y));
    float2 f2 = __half22float2(*reinterpret_cast<__half2*>(&v.z));
    float2 f3 = __half22float2(*reinterpret_cast<__half2*>(&v.w));
    acc[0] += f0.x; acc[1] += f0.y;
    acc[2] += f1.x; acc[3] += f1.y;
    acc[4] += f2.x; acc[5] += f2.y;
    acc[6] += f3.x; acc[7] += f3.y;
}

// gather layer 1: agg[d] = dinv[d]*(hs1[d] + sum hs1[src]), half2 streaming write.
// 4 nodes per warp, 8 lanes (16B each) per node. Index loads software-pipelined.
__global__ void k_gather1(int n) {
    int warp = threadIdx.x >> 5, lane = threadIdx.x & 31;
    int grp = lane >> 3, sub = lane & 7;
    int d = (blockIdx.x * 8 + warp) * 4 + grp;
    bool active = d < n;
    int start = 0, len = 0;
    if (active) { start = g_rowptr[d]; len = g_cnt[d]; }
    float acc[8] = {0, 0, 0, 0, 0, 0, 0, 0};
    if (active) acc_add(acc, __ldg((const uint4*)g_h + (size_t)d * 8 + sub));  // self
    int maxlen = len;
    maxlen = max(maxlen, __shfl_xor_sync(0xffffffffu, maxlen, 8));
    maxlen = max(maxlen, __shfl_xor_sync(0xffffffffu, maxlen, 16));
    // Prefetch round 0 indices, then pipeline: load round j+1 while using round j.
    int sidx = (sub < len) ? __ldcs(&g_srcs[start + sub]) : -1;
    for (int j0 = 0; j0 < maxlen; j0 += 8) {
        int nxt = j0 + 8;
        int sidx_next = (nxt < maxlen && sub < len - nxt)
                            ? __ldcs(&g_srcs[start + nxt + sub]) : -1;
#pragma unroll
        for (int j = 0; j < 8; j++) {
            int s = __shfl_sync(0xffffffffu, sidx, grp * 8 + j);
            if (s >= 0)
                acc_add(acc, __ldg((const uint4*)g_h + (size_t)s * 8 + sub));
        }
        sidx = sidx_next;
    }
    if (active) {
        float di = g_dinv[d];
        __half2 p0 = __floats2half2_rn(acc[0] * di, acc[1] * di);
        __half2 p1 = __floats2half2_rn(acc[2] * di, acc[3] * di);
        __half2 p2 = __floats2half2_rn(acc[4] * di, acc[5] * di);
        __half2 p3 = __floats2half2_rn(acc[6] * di, acc[7] * di);
        uint4 o;
        o.x = *reinterpret_cast<uint32_t*>(&p0);
        o.y = *reinterpret_cast<uint32_t*>(&p1);
        o.z = *reinterpret_cast<uint32_t*>(&p2);
        o.w = *reinterpret_cast<uint32_t*>(&p3);
        __stwt((uint4*)g_agg + (size_t)d * 8 + sub, o);  // bypass L2 (protect g_h)
    }
}

__global__ void k_out_init(const float* __restrict__ bfc, float* __restrict__ out, int B) {
    int g = blockIdx.x * blockDim.x + threadIdx.x;
    if (g < B) out[g] = bfc[0];
}

// gather layer 2 + relu+b2 + FC head. Same pipelined index loads.
__global__ void k_gather2_fc(const float* __restrict__ b2, const float* __restrict__ Wfc,
                             float* __restrict__ out, int n) {
    int warp = threadIdx.x >> 5, lane = threadIdx.x & 31;
    int grp = lane >> 3, sub = lane & 7;
    int d = (blockIdx.x * 8 + warp) * 4 + grp;
    bool active = d < n;
    int start = 0, len = 0;
    if (active) { start = g_rowptr[d]; len = g_cnt[d]; }
    float acc[8] = {0, 0, 0, 0, 0, 0, 0, 0};
    if (active) acc_add(acc, __ldg((const uint4*)g_h + (size_t)d * 8 + sub));  // self
    int maxlen = len;
    maxlen = max(maxlen, __shfl_xor_sync(0xffffffffu, maxlen, 8));
    maxlen = max(maxlen, __shfl_xor_sync(0xffffffffu, maxlen, 16));
    int sidx = (sub < len) ? __ldcs(&g_srcs[start + sub]) : -1;
    for (int j0 = 0; j0 < maxlen; j0 += 8) {
        int nxt = j0 + 8;
        int sidx_next = (nxt < maxlen && sub < len - nxt)
                            ? __ldcs(&g_srcs[start + nxt + sub]) : -1;
#pragma unroll
        for (int j = 0; j < 8; j++) {
            int s = __shfl_sync(0xffffffffu, sidx, grp * 8 + j);
            if (s >= 0)
                acc_add(acc, __ldg((const uint4*)g_h + (size_t)s * 8 + sub));
        }
        sidx = sidx_next;
    }
    float p = 0.f;
    if (active) {
        float di = g_dinv[d];
        int pos = d % 14;
        const float* wrow = Wfc + pos * 64 + sub * 8;
        const float* brow = b2 + sub * 8;
#pragma unroll
        for (int i = 0; i < 8; i++) {
            float t = fmaxf(fmaf(acc[i], di, __ldg(brow + i)), 0.f);
            p = fmaf(t, __ldg(wrow + i), p);
        }
    }
    p += __shfl_down_sync(0xffffffffu, p, 4, 8);
    p += __shfl_down_sync(0xffffffffu, p, 2, 8);
    p += __shfl_down_sync(0xffffffffu, p, 1, 8);
    if (active && sub == 0) atomicAdd(&out[d / 14], p);
}

// ---------------------------------------------------------------------------
extern "C" void kernel_launch(void* const* d_in, const int* in_sizes, int n_in,
                              void* d_out, int out_size) {
    const float* x     = (const float*)d_in[0];
    const int*   edges = (const int*)d_in[1];   // int32 (JAX x64 disabled)
    const float* W1    = (const float*)d_in[2];
    const float* b1    = (const float*)d_in[3];
    const float* W2    = (const float*)d_in[4];
    const float* b2    = (const float*)d_in[5];
    const float* Wfc   = (const float*)d_in[6];
    const float* bfc   = (const float*)d_in[7];
    float* out = (float*)d_out;

    int n = in_sizes[0] / 32;   // 700000
    int E = in_sizes[1] / 2;    // 4000000
    int B = n / 14;             // 50000
    const int* src = edges;
    const int* dst = edges + E;
    int E4 = E / 4, Etail = E - E4 * 4;
    int nb = (n + SCAN_B - 1) / SCAN_B;

    // One-time host-side setup (first call = correctness run, outside capture).
    static cudaStream_t s1 = nullptr, s2 = nullptr;
    static cudaEvent_t e0 = nullptr, eDinv = nullptr, e1 = nullptr, e2 = nullptr;
    if (!s1) {
        cudaStreamCreateWithFlags(&s1, cudaStreamNonBlocking);
        cudaStreamCreateWithFlags(&s2, cudaStreamNonBlocking);
        cudaEventCreateWithFlags(&e0, cudaEventDisableTiming);
        cudaEventCreateWithFlags(&eDinv, cudaEventDisableTiming);
        cudaEventCreateWithFlags(&e1, cudaEventDisableTiming);
        cudaEventCreateWithFlags(&e2, cudaEventDisableTiming);
    }

    // Degree count (launch stream)
    k_zero_cnt<<<(n + 255) / 256, 256>>>(n);
    k_cnt4<<<(E4 + 255) / 256, 256>>>((const int4*)dst, E4);
    if (Etail) k_cnt_tail<<<1, 256>>>(dst, E4 * 4, E);
    cudaEventRecord(e0, 0);

    // Branch A (s1): scan (+dinv fused) -> finalize (+scan2 fused) -> fill
    cudaStreamWaitEvent(s1, e0, 0);
    k_scan1<<<nb, SCAN_B, 0, s1>>>(n);
    cudaEventRecord(eDinv, s1);
    k_scan3<<<(n + 255) / 256, 256, 0, s1>>>(n);
    k_fill4<<<(E4 + 255) / 256, 256, 0, s1>>>((const int4*)src, (const int4*)dst, E4);
    if (Etail) k_fill_tail<<<1, 256, 0, s1>>>(src, dst, E4 * 4, E);
    cudaEventRecord(e1, s1);

    // Branch B (s2): gemm1 (tensor core, needs dinv from scan1) + out init
    cudaStreamWaitEvent(s2, eDinv, 0);
    k_gemm1_mma<<<(n + 127) / 128, 256, 0, s2>>>(x, W1, n);
    k_out_init<<<(B + 255) / 256, 256, 0, s2>>>(bfc, out, B);
    cudaEventRecord(e2, s2);

    // Join on launch stream
    cudaStreamWaitEvent(0, e1, 0);
    cudaStreamWaitEvent(0, e2, 0);

    // Layer 1 gather
    k_gather1<<<(n + 31) / 32, 256>>>(n);

    // Layer 2 (tensor core)
    k_gemm2_mma<<<(n + 127) / 128, 256>>>(W2, b1, n);

    // FC head fused into layer-2 gather
    k_gather2_fc<<<(n + 31) / 32, 256>>>(b2, Wfc, out, n);
}